// round 3
// baseline (speedup 1.0000x reference)
#include <cuda_runtime.h>

#define FULLM 0xFFFFFFFFu
#define NQ 10
#define NL 4

// Amp index i in [0,1024), wire q <-> bit (9-q) (wire 0 = MSB).
// Thread tid owns amps i = (k<<8)|tid, k in 0..3:
//   k bit1 = wire0, k bit0 = wire1 (register-local)
//   tid bit7 = wire2, bit6 = wire3, bit5 = wire4 (smem octet)
//   lane bits 4..0 = wires 5..9 (warp shuffle)

// Composed CNOT-ring gather permutation: new[i] = old[sigma(i)].
// Linear over GF(2): sigma(a^b) = sigma(a)^sigma(b).
__device__ constexpr int sigma_c(int src) {
  src ^= ((src >> 0) & 1) << 9;  // (9,0)
  src ^= ((src >> 1) & 1) << 0;  // (8,9)
  src ^= ((src >> 2) & 1) << 1;  // (7,8)
  src ^= ((src >> 3) & 1) << 2;  // (6,7)
  src ^= ((src >> 4) & 1) << 3;  // (5,6)
  src ^= ((src >> 5) & 1) << 4;  // (4,5)
  src ^= ((src >> 6) & 1) << 5;  // (3,4)
  src ^= ((src >> 7) & 1) << 6;  // (2,3)
  src ^= ((src >> 8) & 1) << 7;  // (1,2)
  src ^= ((src >> 9) & 1) << 8;  // (0,1)
  return src;
}

// RY butterfly, this thread on the t side: lo' = c*lo - s*hi ; hi' = s*lo + c*hi
__device__ __forceinline__ float bfly(float lo, float hi, float c, float s, bool t) {
  return t ? fmaf(s, lo, c * hi) : fmaf(-s, hi, c * lo);
}

__global__ void __launch_bounds__(256)
hqh_kernel(const float* __restrict__ x,
           const float* __restrict__ params,
           float* __restrict__ out,
           int nTok)
{
  __shared__ float buf[2][1024];
  __shared__ float pc[NL * NQ], ps[NL * NQ];
  __shared__ float red[8][20];
  __shared__ float zbs[NQ], xbs[NQ];

  const int tid  = threadIdx.x;
  const int lane = tid & 31;
  const int wid  = tid >> 5;

  // all 40 param sincos once per block
  if (tid < NL * NQ) {
    float s, c;
    __sincosf(0.5f * params[tid], &s, &c);
    pc[tid] = c; ps[tid] = s;
  }
  __syncthreads();

  const bool t2 = (tid >> 7) & 1, t3 = (tid >> 6) & 1, t4 = (tid >> 5) & 1;
  const bool t5 = (lane >> 4) & 1, t6 = (lane >> 3) & 1;
  const bool t7 = (lane >> 2) & 1, t8 = (lane >> 1) & 1, t9 = lane & 1;
  const int sigLow = sigma_c(tid & 31);   // runtime part of octet addresses
  const int sigTid = sigma_c(tid);

  float a[4];
  // layer 0 on |0...0> -> product state (closed form)
  {
    float base = 1.f;
    #pragma unroll
    for (int q = 2; q < NQ; q++)
      base *= ((tid >> (9 - q)) & 1) ? ps[q] : pc[q];
    a[0] = base * pc[0] * pc[1];
    a[1] = base * pc[0] * ps[1];
    a[2] = base * ps[0] * pc[1];
    a[3] = base * ps[0] * ps[1];
  }

  int pb = 0;
  #pragma unroll
  for (int l = 1; l < NL; l++) {
    const float* C = pc + l * NQ;
    const float* S = ps + l * NQ;

    // one smem round: CNOT-ring of layer l-1 fused with RY(l) wires 2..4
    #pragma unroll
    for (int k = 0; k < 4; k++) buf[pb][(k << 8) | tid] = a[k];
    __syncthreads();
    {
      const float c2 = C[2], s2 = S[2], c3 = C[3], s3 = S[3], c4 = C[4], s4 = S[4];
      #pragma unroll
      for (int k = 0; k < 4; k++) {
        float v[8];
        #pragma unroll
        for (int o = 0; o < 8; o++)          // o bit2->wire2(bit7), bit1->wire3, bit0->wire4
          v[o] = buf[pb][sigma_c((k << 8) | (o << 5)) ^ sigLow];
        float w0 = bfly(v[0], v[1], c4, s4, t4);
        float w1 = bfly(v[2], v[3], c4, s4, t4);
        float w2 = bfly(v[4], v[5], c4, s4, t4);
        float w3 = bfly(v[6], v[7], c4, s4, t4);
        float u0 = bfly(w0, w1, c3, s3, t3);
        float u1 = bfly(w2, w3, c3, s3, t3);
        a[k] = bfly(u0, u1, c2, s2, t2);
      }
    }
    pb ^= 1;

    // RY wires 0,1 (k-local)
    {
      const float c0 = C[0], s0 = S[0], c1 = C[1], s1 = S[1];
      float l0 = a[0], h0 = a[2], l1 = a[1], h1 = a[3];
      a[0] = c0 * l0 - s0 * h0;  a[2] = fmaf(s0, l0, c0 * h0);
      a[1] = c0 * l1 - s0 * h1;  a[3] = fmaf(s0, l1, c0 * h1);
      l0 = a[0]; h0 = a[1]; l1 = a[2]; h1 = a[3];
      a[0] = c1 * l0 - s1 * h0;  a[1] = fmaf(s1, l0, c1 * h0);
      a[2] = c1 * l1 - s1 * h1;  a[3] = fmaf(s1, l1, c1 * h1);
    }
    // RY wires 5,6 fused rank-4 (masks 16, 8)
    {
      const float cA = C[5], sA = t5 ? S[5] : -S[5];
      const float cB = C[6], sB = t6 ? S[6] : -S[6];
      const float k00 = cA * cB, k01 = cA * sB, k10 = sA * cB, k11 = sA * sB;
      #pragma unroll
      for (int k = 0; k < 4; k++) {
        float vB  = __shfl_xor_sync(FULLM, a[k], 8);
        float vA  = __shfl_xor_sync(FULLM, a[k], 16);
        float vAB = __shfl_xor_sync(FULLM, a[k], 24);
        a[k] = fmaf(k00, a[k], fmaf(k01, vB, fmaf(k10, vA, k11 * vAB)));
      }
    }
    // RY wires 7,8 fused rank-4 (masks 4, 2)
    {
      const float cA = C[7], sA = t7 ? S[7] : -S[7];
      const float cB = C[8], sB = t8 ? S[8] : -S[8];
      const float k00 = cA * cB, k01 = cA * sB, k10 = sA * cB, k11 = sA * sB;
      #pragma unroll
      for (int k = 0; k < 4; k++) {
        float vB  = __shfl_xor_sync(FULLM, a[k], 2);
        float vA  = __shfl_xor_sync(FULLM, a[k], 4);
        float vAB = __shfl_xor_sync(FULLM, a[k], 6);
        a[k] = fmaf(k00, a[k], fmaf(k01, vB, fmaf(k10, vA, k11 * vAB)));
      }
    }
    // RY wire 9 (mask 1)
    {
      const float c9 = C[9], s9 = t9 ? S[9] : -S[9];
      #pragma unroll
      for (int k = 0; k < 4; k++) {
        float p = __shfl_xor_sync(FULLM, a[k], 1);
        a[k] = fmaf(c9, a[k], s9 * p);
      }
    }
  }

  // final CNOT-ring (layer 3) via gather; same buffer also serves wire2-4 partners
  #pragma unroll
  for (int k = 0; k < 4; k++) buf[pb][(k << 8) | tid] = a[k];
  __syncthreads();
  #pragma unroll
  for (int k = 0; k < 4; k++) a[k] = buf[pb][sigma_c(k << 8) ^ sigTid];

  // observables Zb[q], Xb[q] of the base state
  float p4[4];
  #pragma unroll
  for (int k = 0; k < 4; k++) p4[k] = a[k] * a[k];
  const float ptot = p4[0] + p4[1] + p4[2] + p4[3];

  float zc[NQ], xc[NQ];
  zc[0] = p4[0] + p4[1] - p4[2] - p4[3];
  xc[0] = 2.f * (a[0] * a[2] + a[1] * a[3]);
  zc[1] = p4[0] - p4[1] + p4[2] - p4[3];
  xc[1] = 2.f * (a[0] * a[1] + a[2] * a[3]);
  #pragma unroll
  for (int q = 2; q <= 4; q++) {
    const int m = 1 << (9 - q);
    zc[q] = (tid & m) ? -ptot : ptot;
    float s = 0.f;
    #pragma unroll
    for (int k = 0; k < 4; k++)
      s = fmaf(a[k], buf[pb][sigma_c(k << 8) ^ sigTid ^ sigma_c(m)], s);
    xc[q] = s;
  }
  #pragma unroll
  for (int q = 5; q < NQ; q++) {
    const int m = 1 << (9 - q);
    zc[q] = (lane & m) ? -ptot : ptot;
    float s = 0.f;
    #pragma unroll
    for (int k = 0; k < 4; k++)
      s = fmaf(a[k], __shfl_xor_sync(FULLM, a[k], m), s);
    xc[q] = s;
  }

  // reduce: warp shfl -> 8x20 smem -> 20 finishers
  #pragma unroll
  for (int j = 0; j < 20; j++) {
    float v = (j < NQ) ? zc[j] : xc[j - NQ];
    #pragma unroll
    for (int m = 16; m >= 1; m >>= 1) v += __shfl_xor_sync(FULLM, v, m);
    if (lane == 0) red[wid][j] = v;
  }
  __syncthreads();
  if (tid < 20) {
    float s = 0.f;
    #pragma unroll
    for (int w = 0; w < 8; w++) s += red[w][tid];
    if (tid < NQ) zbs[tid] = s; else xbs[tid - NQ] = s;
  }
  __syncthreads();

  // main: out[t][c] = (c<10) ? cos(x)*Zb[c] - sin(x)*Xb[c] : 0
  const int total4 = nTok * 16;  // 16 float4 per token row of 64
  const float4* __restrict__ x4 = (const float4*)x;
  float4* __restrict__ o4 = (float4*)out;
  for (int idx = blockIdx.x * blockDim.x + threadIdx.x; idx < total4;
       idx += gridDim.x * blockDim.x) {
    const int c4 = idx & 15;
    float4 o = make_float4(0.f, 0.f, 0.f, 0.f);
    if (c4 < 3) {
      const float4 xv = x4[idx];
      const int q0 = c4 * 4;
      float s0, c0, s1, c1;
      __sincosf(xv.x, &s0, &c0); o.x = c0 * zbs[q0]     - s0 * xbs[q0];
      __sincosf(xv.y, &s1, &c1); o.y = c1 * zbs[q0 + 1] - s1 * xbs[q0 + 1];
      if (c4 < 2) {
        float s2, c2, s3, c3;
        __sincosf(xv.z, &s2, &c2); o.z = c2 * zbs[q0 + 2] - s2 * xbs[q0 + 2];
        __sincosf(xv.w, &s3, &c3); o.w = c3 * zbs[q0 + 3] - s3 * xbs[q0 + 3];
      }
    }
    o4[idx] = o;
  }
}

extern "C" void kernel_launch(void* const* d_in, const int* in_sizes, int n_in,
                              void* d_out, int out_size) {
  const float* x = (const float*)d_in[0];
  const float* params = (const float*)d_in[1];
  if (n_in >= 2 && in_sizes[0] == NL * NQ) {   // robust to input ordering
    params = (const float*)d_in[0];
    x = (const float*)d_in[1];
  }
  const int nTok = out_size / 64;
  hqh_kernel<<<296, 256>>>(x, params, (float*)d_out, nTok);  // 2 blocks/SM
}